// round 5
// baseline (speedup 1.0000x reference)
#include <cuda_runtime.h>
#include <cuda_bf16.h>

// Problem constants (from reference):
//   T=4 tables, E=1,000,000 rows/table, D=128 dim, B=8192 bags, L=32 bag length
//   indices: [T, B, L]  (d_in: 1,048,576 elems)  -- int32 in practice (JAX x64 off)
//   weights: [T, E, D] float32 (d_in: 512,000,000 elems)
//   output:  [B, T*D] float32: out[b, t*D + d] = sum_l weights[t, indices[t,b,l], d]

#define T_TABLES 4
#define E_ROWS   1000000
#define D_DIM    128
#define B_BATCH  8192
#define L_BAG    32

// One warp per (t, b) bag. Lane k owns float4 chunk k of the D=128 row.
// L == 32 == warpSize: each lane loads exactly one bag index (int32, 128B
// coalesced per warp), row indices broadcast via shuffles. Fully unrolled so
// ptxas front-batches the 32 independent LDG.128s per lane for deep MLP.
__global__ __launch_bounds__(256, 8)
void embedding_bag_sum_kernel(const int* __restrict__ indices,
                              const float* __restrict__ weights,
                              float* __restrict__ out)
{
    const int gtid = blockIdx.x * blockDim.x + threadIdx.x;
    const int warp = gtid >> 5;               // 0 .. T*B-1
    const int lane = threadIdx.x & 31;

    if (warp >= T_TABLES * B_BATCH) return;

    const int t = warp >> 13;                 // warp / B  (B = 8192 = 2^13)
    const int b = warp & (B_BATCH - 1);       // warp % B

    // Each lane loads one of the 32 bag indices (coalesced 128B per warp).
    const int* bag = indices + ((size_t)t * B_BATCH + b) * L_BAG;
    int my_idx = __ldg(bag + lane);

    const float4* wt = reinterpret_cast<const float4*>(
        weights + (size_t)t * E_ROWS * D_DIM);

    float4 acc = make_float4(0.f, 0.f, 0.f, 0.f);

    #pragma unroll
    for (int l = 0; l < L_BAG; ++l) {
        int row = __shfl_sync(0xffffffffu, my_idx, l);
        // Defensive: if dtype/layout theory is wrong, fail with rel_err,
        // not an illegal access. Free in the correct case (predicated load).
        if ((unsigned)row < (unsigned)E_ROWS) {
            // row has D/4 = 32 float4s; lane k reads float4 k -> 512B/warp
            float4 v = __ldg(wt + (size_t)row * (D_DIM / 4) + lane);
            acc.x += v.x;
            acc.y += v.y;
            acc.z += v.z;
            acc.w += v.w;
        }
    }

    // out[b, t*D + d] as float4: index = b*128 + t*32 + lane
    float4* out4 = reinterpret_cast<float4*>(out);
    out4[(size_t)b * (T_TABLES * D_DIM / 4) + t * (D_DIM / 4) + lane] = acc;
}

extern "C" void kernel_launch(void* const* d_in, const int* in_sizes, int n_in,
                              void* d_out, int out_size)
{
    // Identify inputs by element count (robust to metadata ordering):
    //   indices: T*B*L = 1,048,576 ; weights: T*E*D = 512,000,000
    const void* p0 = d_in[0];
    const void* p1 = (n_in > 1) ? d_in[1] : d_in[0];
    const int*   indices;
    const float* weights;
    if (in_sizes[0] < in_sizes[1]) {
        indices = (const int*)p0;
        weights = (const float*)p1;
    } else {
        indices = (const int*)p1;
        weights = (const float*)p0;
    }
    float* out = (float*)d_out;

    const int total_warps = T_TABLES * B_BATCH;           // 32768
    const int threads     = 256;                          // 8 warps/CTA
    const int blocks      = (total_warps * 32) / threads; // 4096

    embedding_bag_sum_kernel<<<blocks, threads>>>(indices, weights, out);
}

// round 7
// speedup vs baseline: 1.0312x; 1.0312x over previous
#include <cuda_runtime.h>
#include <cuda_bf16.h>

// Problem constants:
//   T=4 tables, E=1,000,000 rows/table, D=128 dim, B=8192 bags, L=32 bag length
//   indices: [T, B, L] int32 (1,048,576 elems)
//   weights: [T, E, D] float32 (512,000,000 elems)
//   output:  [B, T*D] float32: out[b, t*D + d] = sum_l weights[t, indices[t,b,l], d]

#define T_TABLES 4
#define E_ROWS   1000000
#define D_DIM    128
#define B_BATCH  8192
#define L_BAG    32
#define BATCH    8   // rows buffered per stage (8 x float4 = 32 regs of MLP)

// One warp per (t, b) bag. Lane k owns float4 chunk k of the D=128 row.
// Each lane loads one bag index (int32, 128B coalesced/warp); row indices are
// shuffle-broadcast. Loads are software-batched BATCH-deep into a register
// buffer so ptxas emits front-batched independent LDG.128 runs (deep MLP to
// cover the ~577-cycle DRAM latency), then accumulated.
__global__ __launch_bounds__(256, 4)
void embedding_bag_sum_kernel(const int* __restrict__ indices,
                              const float* __restrict__ weights,
                              float* __restrict__ out)
{
    const int gtid = blockIdx.x * blockDim.x + threadIdx.x;
    const int warp = gtid >> 5;               // 0 .. T*B-1 (grid is exact)
    const int lane = threadIdx.x & 31;

    const int t = warp >> 13;                 // warp / B  (B = 8192 = 2^13)
    const int b = warp & (B_BATCH - 1);       // warp % B

    const int* bag = indices + ((size_t)t * B_BATCH + b) * L_BAG;
    int my_idx = __ldg(bag + lane);

    const float4* wt = reinterpret_cast<const float4*>(
        weights + (size_t)t * E_ROWS * D_DIM);

    float4 acc = make_float4(0.f, 0.f, 0.f, 0.f);

    #pragma unroll
    for (int stage = 0; stage < L_BAG / BATCH; ++stage) {
        float4 v[BATCH];
        // Batch of BATCH independent gathers -> front-batched LDG.128s.
        #pragma unroll
        for (int j = 0; j < BATCH; ++j) {
            int row = __shfl_sync(0xffffffffu, my_idx, stage * BATCH + j);
            // Defensive clamp: malformed index degrades to rel_err, not a crash.
            if ((unsigned)row >= (unsigned)E_ROWS) row = 0;
            v[j] = __ldg(wt + (size_t)row * (D_DIM / 4) + lane);
        }
        #pragma unroll
        for (int j = 0; j < BATCH; ++j) {
            acc.x += v[j].x;
            acc.y += v[j].y;
            acc.z += v[j].z;
            acc.w += v[j].w;
        }
    }

    // out[b, t*D + d] as float4: index = b*128 + t*32 + lane
    float4* out4 = reinterpret_cast<float4*>(out);
    out4[(size_t)b * (T_TABLES * D_DIM / 4) + t * (D_DIM / 4) + lane] = acc;
}

extern "C" void kernel_launch(void* const* d_in, const int* in_sizes, int n_in,
                              void* d_out, int out_size)
{
    // Identify inputs by element count (robust to metadata ordering):
    //   indices: T*B*L = 1,048,576 ; weights: T*E*D = 512,000,000
    const int*   indices;
    const float* weights;
    if (in_sizes[0] < in_sizes[1]) {
        indices = (const int*)d_in[0];
        weights = (const float*)d_in[1];
    } else {
        indices = (const int*)d_in[1];
        weights = (const float*)d_in[0];
    }
    float* out = (float*)d_out;

    const int total_warps = T_TABLES * B_BATCH;           // 32768
    const int threads     = 256;                          // 8 warps/CTA
    const int blocks      = (total_warps * 32) / threads; // 4096

    embedding_bag_sum_kernel<<<blocks, threads>>>(indices, weights, out);
}

// round 10
// speedup vs baseline: 1.0489x; 1.0171x over previous
#include <cuda_runtime.h>
#include <cuda_bf16.h>

// Problem constants:
//   T=4 tables, E=1,000,000 rows/table, D=128 dim, B=8192 bags, L=32 bag length
//   indices: [T, B, L] int32 (1,048,576 elems)
//   weights: [T, E, D] float32 (512,000,000 elems)
//   output:  [B, T*D] float32: out[b, t*D + d] = sum_l weights[t, indices[t,b,l], d]

#define T_TABLES 4
#define E_ROWS   1000000
#define D_DIM    128
#define B_BATCH  8192
#define L_BAG    32
#define BATCH    16  // rows buffered per stage (16 x float4 = 64 regs of MLP)

// One warp per (t, b) bag. Lane k owns float4 chunk k of the D=128 row.
// Each lane loads one bag index (int32, 128B coalesced/warp, clamped once);
// row indices are shuffle-broadcast. Loads are software-batched 16-deep into
// a register buffer -> 16 front-batched independent LDG.128s per warp.
// 3 CTAs/SM x 8 warps x 16 = 384 outstanding loads/SM to saturate DRAM.
__global__ __launch_bounds__(256, 3)
void embedding_bag_sum_kernel(const int* __restrict__ indices,
                              const float* __restrict__ weights,
                              float* __restrict__ out)
{
    const int gtid = blockIdx.x * blockDim.x + threadIdx.x;
    const int warp = gtid >> 5;               // 0 .. T*B-1 (grid is exact)
    const int lane = threadIdx.x & 31;

    const int t = warp >> 13;                 // warp / B  (B = 8192 = 2^13)
    const int b = warp & (B_BATCH - 1);       // warp % B

    const int* bag = indices + ((size_t)t * B_BATCH + b) * L_BAG;
    int my_idx = __ldg(bag + lane);
    // Clamp once per lane (not per shuffled load): malformed index degrades
    // to rel_err, never an illegal access.
    if ((unsigned)my_idx >= (unsigned)E_ROWS) my_idx = 0;

    const float4* wt = reinterpret_cast<const float4*>(
        weights + (size_t)t * E_ROWS * D_DIM);

    float4 acc = make_float4(0.f, 0.f, 0.f, 0.f);

    #pragma unroll
    for (int stage = 0; stage < L_BAG / BATCH; ++stage) {
        float4 v[BATCH];
        #pragma unroll
        for (int j = 0; j < BATCH; ++j) {
            int row = __shfl_sync(0xffffffffu, my_idx, stage * BATCH + j);
            v[j] = __ldg(wt + (size_t)row * (D_DIM / 4) + lane);
        }
        #pragma unroll
        for (int j = 0; j < BATCH; ++j) {
            acc.x += v[j].x;
            acc.y += v[j].y;
            acc.z += v[j].z;
            acc.w += v[j].w;
        }
    }

    // out[b, t*D + d] as float4: index = b*128 + t*32 + lane
    float4* out4 = reinterpret_cast<float4*>(out);
    out4[(size_t)b * (T_TABLES * D_DIM / 4) + t * (D_DIM / 4) + lane] = acc;
}

extern "C" void kernel_launch(void* const* d_in, const int* in_sizes, int n_in,
                              void* d_out, int out_size)
{
    // Identify inputs by element count (robust to metadata ordering):
    //   indices: T*B*L = 1,048,576 ; weights: T*E*D = 512,000,000
    const int*   indices;
    const float* weights;
    if (in_sizes[0] < in_sizes[1]) {
        indices = (const int*)d_in[0];
        weights = (const float*)d_in[1];
    } else {
        indices = (const int*)d_in[1];
        weights = (const float*)d_in[0];
    }
    float* out = (float*)d_out;

    const int total_warps = T_TABLES * B_BATCH;           // 32768
    const int threads     = 256;                          // 8 warps/CTA
    const int blocks      = (total_warps * 32) / threads; // 4096

    embedding_bag_sum_kernel<<<blocks, threads>>>(indices, weights, out);
}